// round 6
// baseline (speedup 1.0000x reference)
#include <cuda_runtime.h>
#include <cstdint>
#include <cstddef>

#define NN 100000
#define NE 640000

typedef unsigned long long u64t;

__device__ float g_pre[(size_t)NN * 128];   // [n][0:64]=x@Wa+eb1, [64:128]=x@Wb
__device__ float g_agg[(size_t)NN * 128];   // scatter-sum of e2
__device__ float g_cnt[NN];                 // edge counts per dest node
__device__ int   g_is64;                    // edge_index dtype flag (1 = int64)

// ---------- packed f32x2 helpers ----------
__device__ __forceinline__ u64t pk2(float lo, float hi) {
    u64t r; asm("mov.b64 %0,{%1,%2};" : "=l"(r) : "f"(lo), "f"(hi)); return r;
}
__device__ __forceinline__ float2 upk(u64t v) {
    float2 r; asm("mov.b64 {%0,%1},%2;" : "=f"(r.x), "=f"(r.y) : "l"(v)); return r;
}
__device__ __forceinline__ void fma2(u64t& d, u64t a, u64t b) {
    asm("fma.rn.f32x2 %0,%1,%2,%0;" : "+l"(d) : "l"(a), "l"(b));
}

// ------------------ detect edge_index element width -------------------
__global__ void k_detect(const unsigned int* __restrict__ w) {
    unsigned int any = 0;
    for (int i = threadIdx.x; i < 1024; i += 32) any |= w[2 * i + 1];
#pragma unroll
    for (int o = 16; o > 0; o >>= 1) any |= __shfl_xor_sync(0xffffffffu, any, o);
    if (threadIdx.x == 0) g_is64 = (any == 0) ? 1 : 0;
}

// ---------------------------- zero scratch ----------------------------
__global__ void k_zero() {
    size_t i = (size_t)blockIdx.x * blockDim.x + threadIdx.x;
    size_t stride = (size_t)gridDim.x * blockDim.x;
    float4* a4 = (float4*)g_agg;
    const size_t n4 = (size_t)NN * 32;
    for (size_t j = i; j < n4; j += stride) a4[j] = make_float4(0.f, 0.f, 0.f, 0.f);
    for (size_t j = i; j < (size_t)NN; j += stride) g_cnt[j] = 0.f;
}

// ------------- kernel 1: pre[n] = x @ [Wa|Wb] (+eb1), weights via LDG -----------
__global__ void __launch_bounds__(256, 2) k_pre(
    const float* __restrict__ x, const float* __restrict__ ew1,
    const float* __restrict__ eb1) {
    extern __shared__ float sm[];
    float* sX = sm;             // 128*132 = 16896
    const int tid = threadIdx.x;
    const int n0 = blockIdx.x * 128;

#pragma unroll
    for (int it = 0; it < 16; ++it) {
        int idx = tid + it * 256;
        int r = idx >> 5, q = idx & 31;
        int n = n0 + r;
        float4 v = make_float4(0.f, 0.f, 0.f, 0.f);
        if (n < NN) v = __ldg((const float4*)(x + (size_t)n * 128) + q);
        *(float4*)(sX + r * 132 + q * 4) = v;
    }
    __syncthreads();

    const int tx = tid & 31, ty = tid >> 5;
    const int c0 = ty * 16;
    // weight base: cols c0..c0+15 of [Wa|Wb]; Wa rows at ew1, Wb rows at ew1+8192
    const ulonglong2* wp = (const ulonglong2*)(ew1 + (c0 < 64 ? c0 : 8192 + (c0 - 64)));
    u64t acc[4][8];
#pragma unroll
    for (int i = 0; i < 4; i++)
#pragma unroll
        for (int p = 0; p < 8; p++) acc[i][p] = 0ull;

    const float* er[4];
#pragma unroll
    for (int i = 0; i < 4; i++) er[i] = sX + (tx + 32 * i) * 132;

#pragma unroll 4
    for (int k0 = 0; k0 < 128; k0 += 4) {
        float4 av[4];
#pragma unroll
        for (int i = 0; i < 4; i++) av[i] = *(const float4*)(er[i] + k0);
#pragma unroll
        for (int kk = 0; kk < 4; kk++) {
            const ulonglong2* bp = wp + (size_t)(k0 + kk) * 16;
            ulonglong2 b01 = __ldg(bp), b23 = __ldg(bp + 1),
                       b45 = __ldg(bp + 2), b67 = __ldg(bp + 3);
#pragma unroll
            for (int i = 0; i < 4; i++) {
                float a = ((const float*)&av[i])[kk];
                u64t ap = pk2(a, a);
                fma2(acc[i][0], ap, b01.x); fma2(acc[i][1], ap, b01.y);
                fma2(acc[i][2], ap, b23.x); fma2(acc[i][3], ap, b23.y);
                fma2(acc[i][4], ap, b45.x); fma2(acc[i][5], ap, b45.y);
                fma2(acc[i][6], ap, b67.x); fma2(acc[i][7], ap, b67.y);
            }
        }
    }
#pragma unroll
    for (int i = 0; i < 4; i++) {
        int n = n0 + tx + 32 * i;
        if (n >= NN) continue;
        float* dst = g_pre + (size_t)n * 128 + c0;
#pragma unroll
        for (int p = 0; p < 8; p++) {
            float2 v = upk(acc[i][p]);
            int j = c0 + 2 * p;
            if (j < 64)     v.x += __ldg(eb1 + j);
            if (j + 1 < 64) v.y += __ldg(eb1 + j + 1);
            dst[2 * p] = v.x; dst[2 * p + 1] = v.y;
        }
    }
}

// ------------------- kernel 2: edges (weights via LDG, 2 CTAs/SM) ---------------
__global__ void __launch_bounds__(256, 2) k_edge(
    const float* __restrict__ ea, const void* __restrict__ ei_raw,
    const float* __restrict__ ew1, const float* __restrict__ ew2,
    const float* __restrict__ eb2, const float* __restrict__ ne_g,
    const float* __restrict__ ne_b, float* __restrict__ eout) {
    extern __shared__ float sm[];
    float* sE   = sm;                    // 128*132 = 16896
    float* sPAB = sm + 16896;            // 128*68  = 8704 (H written in place)
    int*   sRow = (int*)(sm + 25600);    // 128
    int*   sCol = sRow + 128;            // 128
    float* sEB2 = sm + 25856;            // 128  (total 25984 floats)
    const int tid = threadIdx.x;
    const int e0 = blockIdx.x * 128;
    const int is64 = g_is64;

    if (tid < 128) {
        int e = e0 + tid;
        int r, c;
        if (is64) {
            const long long* p = (const long long*)ei_raw;
            r = (int)__ldg(p + e);
            c = (int)__ldg(p + (size_t)NE + e);
        } else {
            const int* p = (const int*)ei_raw;
            r = __ldg(p + e);
            c = __ldg(p + (size_t)NE + e);
        }
        sRow[tid] = min(max(r, 0), NN - 1);
        sCol[tid] = min(max(c, 0), NN - 1);
        sEB2[tid] = __ldg(eb2 + tid);
    }
    // gather pa[row]+pb[col] — indices read directly from gmem so these L2-latency
    // loads overlap the sE fill below (no intervening barrier).
#pragma unroll
    for (int it = 0; it < 8; ++it) {
        int idx = tid + it * 256;
        int el = idx >> 4, q = idx & 15;
        int e = e0 + el;
        int rn, cn;
        if (is64) {
            const long long* p = (const long long*)ei_raw;
            rn = (int)__ldg(p + e);
            cn = (int)__ldg(p + (size_t)NE + e);
        } else {
            const int* p = (const int*)ei_raw;
            rn = __ldg(p + e);
            cn = __ldg(p + (size_t)NE + e);
        }
        rn = min(max(rn, 0), NN - 1);
        cn = min(max(cn, 0), NN - 1);
        float4 va = __ldg((const float4*)(g_pre + (size_t)rn * 128) + q);
        float4 vb = __ldg((const float4*)(g_pre + (size_t)cn * 128) + 16 + q);
        float* dst = sPAB + el * 68 + q * 4;
        dst[0] = va.x + vb.x; dst[1] = va.y + vb.y;
        dst[2] = va.z + vb.z; dst[3] = va.w + vb.w;
    }
#pragma unroll
    for (int it = 0; it < 16; ++it) {
        int idx = tid + it * 256;
        int r = idx >> 5, q = idx & 31;
        float4 v = __ldg((const float4*)(ea + (size_t)(e0 + r) * 128) + q);
        *(float4*)(sE + r * 132 + q * 4) = v;
    }
    __syncthreads();

    const int tx = tid & 31, ty = tid >> 5;
    // stage 1: H[128][64] = relu(E@We + PAB), H overwrites PAB in place
    {
        const int c0 = ty * 8;
        const ulonglong2* wp = (const ulonglong2*)(ew1 + 16384 + c0);  // We rows
        u64t acc[4][4];
#pragma unroll
        for (int i = 0; i < 4; i++)
#pragma unroll
            for (int p = 0; p < 4; p++) acc[i][p] = 0ull;
        const float* er[4];
#pragma unroll
        for (int i = 0; i < 4; i++) er[i] = sE + (tx + 32 * i) * 132;
#pragma unroll 8
        for (int k0 = 0; k0 < 128; k0 += 4) {
            float4 av[4];
#pragma unroll
            for (int i = 0; i < 4; i++) av[i] = *(const float4*)(er[i] + k0);
#pragma unroll
            for (int kk = 0; kk < 4; kk++) {
                const ulonglong2* bp = wp + (size_t)(k0 + kk) * 16;
                ulonglong2 b01 = __ldg(bp), b23 = __ldg(bp + 1);
#pragma unroll
                for (int i = 0; i < 4; i++) {
                    float a = ((const float*)&av[i])[kk];
                    u64t ap = pk2(a, a);
                    fma2(acc[i][0], ap, b01.x); fma2(acc[i][1], ap, b01.y);
                    fma2(acc[i][2], ap, b23.x); fma2(acc[i][3], ap, b23.y);
                }
            }
        }
#pragma unroll
        for (int i = 0; i < 4; i++) {
            int r = tx + 32 * i;
            float* hd = sPAB + r * 68 + c0;    // read pab, write H same cells
#pragma unroll
            for (int p = 0; p < 4; p++) {
                float2 v = upk(acc[i][p]);
                float p0 = hd[2 * p], p1 = hd[2 * p + 1];
                hd[2 * p]     = fmaxf(v.x + p0, 0.f);
                hd[2 * p + 1] = fmaxf(v.y + p1, 0.f);
            }
        }
    }
    __syncthreads();
    // stage 2: e2 = H@ew2 + eb2 + e  (written back into sE, same-thread cells)
    {
        const int c1 = ty * 16;
        const ulonglong2* wp = (const ulonglong2*)(ew2 + c1);
        u64t acc[4][8];
#pragma unroll
        for (int i = 0; i < 4; i++)
#pragma unroll
            for (int p = 0; p < 8; p++) acc[i][p] = 0ull;
        const float* hr[4];
#pragma unroll
        for (int i = 0; i < 4; i++) hr[i] = sPAB + (tx + 32 * i) * 68;
#pragma unroll 4
        for (int k0 = 0; k0 < 64; k0 += 4) {
            float4 av[4];
#pragma unroll
            for (int i = 0; i < 4; i++) av[i] = *(const float4*)(hr[i] + k0);
#pragma unroll
            for (int kk = 0; kk < 4; kk++) {
                const ulonglong2* bp = wp + (size_t)(k0 + kk) * 32;
                ulonglong2 b01 = __ldg(bp),     b23 = __ldg(bp + 1),
                           b45 = __ldg(bp + 2), b67 = __ldg(bp + 3);
#pragma unroll
                for (int i = 0; i < 4; i++) {
                    float a = ((const float*)&av[i])[kk];
                    u64t ap = pk2(a, a);
                    fma2(acc[i][0], ap, b01.x); fma2(acc[i][1], ap, b01.y);
                    fma2(acc[i][2], ap, b23.x); fma2(acc[i][3], ap, b23.y);
                    fma2(acc[i][4], ap, b45.x); fma2(acc[i][5], ap, b45.y);
                    fma2(acc[i][6], ap, b67.x); fma2(acc[i][7], ap, b67.y);
                }
            }
        }
#pragma unroll
        for (int i = 0; i < 4; i++) {
            int r = tx + 32 * i;
            float* erow = sE + r * 132 + c1;
#pragma unroll
            for (int p = 0; p < 8; p++) {
                float2 v = upk(acc[i][p]);
                int j = c1 + 2 * p;
                erow[2 * p]     += v.x + sEB2[j];
                erow[2 * p + 1] += v.y + sEB2[j + 1];
            }
        }
    }
    __syncthreads();
    // LayerNorm + vector-atomic scatter (2 threads per edge row)
    {
        const int r = tid >> 1, half = tid & 1;
        const float* rowp = sE + r * 132 + half * 64;
        float s = 0.f, s2 = 0.f;
#pragma unroll 8
        for (int k = 0; k < 64; k++) { float t = rowp[k]; s += t; s2 = fmaf(t, t, s2); }
        s  += __shfl_xor_sync(0xffffffffu, s, 1);
        s2 += __shfl_xor_sync(0xffffffffu, s2, 1);
        const float mu  = s * 0.0078125f;
        const float var = fmaf(-mu, mu, s2 * 0.0078125f);
        const float rstd = rsqrtf(var + 1e-5f);
        const int e = e0 + r;
        float* outp = eout + (size_t)e * 128 + half * 64;
        const int cn = sCol[r];
        float4* aggp = (float4*)(g_agg + (size_t)cn * 128 + half * 64);
#pragma unroll
        for (int q = 0; q < 16; q++) {
            float v0 = rowp[4 * q], v1 = rowp[4 * q + 1];
            float v2 = rowp[4 * q + 2], v3 = rowp[4 * q + 3];
            atomicAdd(aggp + q, make_float4(v0, v1, v2, v3));
            int j = half * 64 + 4 * q;
            float4 o;
            o.x = fmaf((v0 - mu) * rstd, __ldg(ne_g + j),     __ldg(ne_b + j));
            o.y = fmaf((v1 - mu) * rstd, __ldg(ne_g + j + 1), __ldg(ne_b + j + 1));
            o.z = fmaf((v2 - mu) * rstd, __ldg(ne_g + j + 2), __ldg(ne_b + j + 2));
            o.w = fmaf((v3 - mu) * rstd, __ldg(ne_g + j + 3), __ldg(ne_b + j + 3));
            *(float4*)(outp + 4 * q) = o;
        }
        if (half == 0) atomicAdd(g_cnt + cn, 1.0f);
    }
}

// ------------------- kernel 3: nodes (64/block, weights via LDG) ----------------
__global__ void __launch_bounds__(256, 2) k_node(
    const float* __restrict__ x, const float* __restrict__ nw1,
    const float* __restrict__ nb1, const float* __restrict__ nw2,
    const float* __restrict__ nb2, const float* __restrict__ nx_g,
    const float* __restrict__ nx_b, float* __restrict__ xout) {
    extern __shared__ float sm[];
    float* sX = sm;              // 64*132 = 8448
    float* sA = sm + 8448;       // 64*132 = 8448
    float* sH = sm + 16896;      // 64*68  = 4352  (total 21248 floats)
    const int tid = threadIdx.x;
    const int n0 = blockIdx.x * 64;

#pragma unroll
    for (int it = 0; it < 8; ++it) {
        int idx = tid + it * 256;
        int r = idx >> 5, q = idx & 31;
        int n = n0 + r;
        float4 v = make_float4(0.f, 0.f, 0.f, 0.f);
        float4 w4 = make_float4(0.f, 0.f, 0.f, 0.f);
        if (n < NN) {
            v = __ldg((const float4*)(x + (size_t)n * 128) + q);
            float c = g_cnt[n];
            float inv = 1.0f / fmaxf(c, 1.0f);
            float4 a = *((const float4*)(g_agg + (size_t)n * 128) + q);
            w4 = make_float4(a.x * inv, a.y * inv, a.z * inv, a.w * inv);
        }
        *(float4*)(sX + r * 132 + q * 4) = v;
        *(float4*)(sA + r * 132 + q * 4) = w4;
    }
    __syncthreads();

    const int tx = tid & 31, ty = tid >> 5;
    const int c0 = ty * 8;
    const ulonglong2* w1p = (const ulonglong2*)(nw1 + c0);
    u64t acc[2][4];
#pragma unroll
    for (int i = 0; i < 2; i++)
#pragma unroll
        for (int p = 0; p < 4; p++) acc[i][p] = 0ull;
    // pass A: x @ nw1[0:128]
    {
        const float* er[2];
#pragma unroll
        for (int i = 0; i < 2; i++) er[i] = sX + (tx + 32 * i) * 132;
#pragma unroll 8
        for (int k0 = 0; k0 < 128; k0 += 4) {
            float4 av[2];
#pragma unroll
            for (int i = 0; i < 2; i++) av[i] = *(const float4*)(er[i] + k0);
#pragma unroll
            for (int kk = 0; kk < 4; kk++) {
                const ulonglong2* bp = w1p + (size_t)(k0 + kk) * 16;
                ulonglong2 b01 = __ldg(bp), b23 = __ldg(bp + 1);
#pragma unroll
                for (int i = 0; i < 2; i++) {
                    float a = ((const float*)&av[i])[kk];
                    u64t ap = pk2(a, a);
                    fma2(acc[i][0], ap, b01.x); fma2(acc[i][1], ap, b01.y);
                    fma2(acc[i][2], ap, b23.x); fma2(acc[i][3], ap, b23.y);
                }
            }
        }
    }
    // pass B: agg @ nw1[128:256]
    {
        const float* er[2];
#pragma unroll
        for (int i = 0; i < 2; i++) er[i] = sA + (tx + 32 * i) * 132;
#pragma unroll 8
        for (int k0 = 0; k0 < 128; k0 += 4) {
            float4 av[2];
#pragma unroll
            for (int i = 0; i < 2; i++) av[i] = *(const float4*)(er[i] + k0);
#pragma unroll
            for (int kk = 0; kk < 4; kk++) {
                const ulonglong2* bp = w1p + (size_t)(128 + k0 + kk) * 16;
                ulonglong2 b01 = __ldg(bp), b23 = __ldg(bp + 1);
#pragma unroll
                for (int i = 0; i < 2; i++) {
                    float a = ((const float*)&av[i])[kk];
                    u64t ap = pk2(a, a);
                    fma2(acc[i][0], ap, b01.x); fma2(acc[i][1], ap, b01.y);
                    fma2(acc[i][2], ap, b23.x); fma2(acc[i][3], ap, b23.y);
                }
            }
        }
    }
#pragma unroll
    for (int i = 0; i < 2; i++) {
        int r = tx + 32 * i;
        float* hd = sH + r * 68 + c0;
#pragma unroll
        for (int p = 0; p < 4; p++) {
            float2 v = upk(acc[i][p]);
            hd[2 * p]     = fmaxf(v.x + __ldg(nb1 + c0 + 2 * p), 0.f);
            hd[2 * p + 1] = fmaxf(v.y + __ldg(nb1 + c0 + 2 * p + 1), 0.f);
        }
    }
    __syncthreads();
    // stage 2: x2 = x + H@nw2 + nb2 (into sX)
    {
        const int c1 = ty * 16;
        const ulonglong2* w2p = (const ulonglong2*)(nw2 + c1);
        u64t acc2[2][8];
#pragma unroll
        for (int i = 0; i < 2; i++)
#pragma unroll
            for (int p = 0; p < 8; p++) acc2[i][p] = 0ull;
        const float* hr[2];
#pragma unroll
        for (int i = 0; i < 2; i++) hr[i] = sH + (tx + 32 * i) * 68;
#pragma unroll 4
        for (int k0 = 0; k0 < 64; k0 += 4) {
            float4 av[2];
#pragma unroll
            for (int i = 0; i < 2; i++) av[i] = *(const float4*)(hr[i] + k0);
#pragma unroll
            for (int kk = 0; kk < 4; kk++) {
                const ulonglong2* bp = w2p + (size_t)(k0 + kk) * 32;
                ulonglong2 b01 = __ldg(bp),     b23 = __ldg(bp + 1),
                           b45 = __ldg(bp + 2), b67 = __ldg(bp + 3);
#pragma unroll
                for (int i = 0; i < 2; i++) {
                    float a = ((const float*)&av[i])[kk];
                    u64t ap = pk2(a, a);
                    fma2(acc2[i][0], ap, b01.x); fma2(acc2[i][1], ap, b01.y);
                    fma2(acc2[i][2], ap, b23.x); fma2(acc2[i][3], ap, b23.y);
                    fma2(acc2[i][4], ap, b45.x); fma2(acc2[i][5], ap, b45.y);
                    fma2(acc2[i][6], ap, b67.x); fma2(acc2[i][7], ap, b67.y);
                }
            }
        }
#pragma unroll
        for (int i = 0; i < 2; i++) {
            int r = tx + 32 * i;
            float* xrow = sX + r * 132 + c1;
#pragma unroll
            for (int p = 0; p < 8; p++) {
                float2 v = upk(acc2[i][p]);
                int j = c1 + 2 * p;
                xrow[2 * p]     += v.x + __ldg(nb2 + j);
                xrow[2 * p + 1] += v.y + __ldg(nb2 + j + 1);
            }
        }
    }
    __syncthreads();
    // LayerNorm -> x_out (4 threads per row, 64 rows)
    {
        const int r = tid >> 2, qtr = tid & 3;
        const float* rowp = sX + r * 132 + qtr * 32;
        float s = 0.f, s2 = 0.f;
#pragma unroll 8
        for (int k = 0; k < 32; k++) { float t = rowp[k]; s += t; s2 = fmaf(t, t, s2); }
        s  += __shfl_xor_sync(0xffffffffu, s, 1);
        s2 += __shfl_xor_sync(0xffffffffu, s2, 1);
        s  += __shfl_xor_sync(0xffffffffu, s, 2);
        s2 += __shfl_xor_sync(0xffffffffu, s2, 2);
        const float mu  = s * 0.0078125f;
        const float var = fmaf(-mu, mu, s2 * 0.0078125f);
        const float rstd = rsqrtf(var + 1e-5f);
        const int n = n0 + r;
        if (n < NN) {
            float* outp = xout + (size_t)n * 128 + qtr * 32;
#pragma unroll
            for (int q = 0; q < 8; q++) {
                float v0 = rowp[4 * q], v1 = rowp[4 * q + 1];
                float v2 = rowp[4 * q + 2], v3 = rowp[4 * q + 3];
                int j = qtr * 32 + 4 * q;
                float4 o;
                o.x = fmaf((v0 - mu) * rstd, __ldg(nx_g + j),     __ldg(nx_b + j));
                o.y = fmaf((v1 - mu) * rstd, __ldg(nx_g + j + 1), __ldg(nx_b + j + 1));
                o.z = fmaf((v2 - mu) * rstd, __ldg(nx_g + j + 2), __ldg(nx_b + j + 2));
                o.w = fmaf((v3 - mu) * rstd, __ldg(nx_g + j + 3), __ldg(nx_b + j + 3));
                *(float4*)(outp + 4 * q) = o;
            }
        }
    }
}

// --------------------------------- launch ---------------------------------------
extern "C" void kernel_launch(void* const* d_in, const int* in_sizes, int n_in,
                              void* d_out, int out_size) {
    const float* x   = (const float*)d_in[0];
    const void*  ei  = d_in[1];               // int32 or int64 — detected on device
    const float* ea  = (const float*)d_in[2];
    const float* ew1 = (const float*)d_in[4];
    const float* eb1 = (const float*)d_in[5];
    const float* ew2 = (const float*)d_in[6];
    const float* eb2 = (const float*)d_in[7];
    const float* nw1 = (const float*)d_in[8];
    const float* nb1 = (const float*)d_in[9];
    const float* nw2 = (const float*)d_in[10];
    const float* nb2 = (const float*)d_in[11];
    const float* nxg = (const float*)d_in[12];
    const float* nxb = (const float*)d_in[13];
    const float* neg_ = (const float*)d_in[14];
    const float* neb_ = (const float*)d_in[15];
    float* xout = (float*)d_out;
    float* eout = xout + (size_t)NN * 128;

    const int SM_PRE  = 16896 * 4;   // 67584
    const int SM_EDGE = 25984 * 4;   // 103936
    const int SM_NODE = 21248 * 4;   // 84992
    cudaFuncSetAttribute(k_pre,  cudaFuncAttributeMaxDynamicSharedMemorySize, SM_PRE);
    cudaFuncSetAttribute(k_edge, cudaFuncAttributeMaxDynamicSharedMemorySize, SM_EDGE);
    cudaFuncSetAttribute(k_node, cudaFuncAttributeMaxDynamicSharedMemorySize, SM_NODE);

    k_detect<<<1, 32>>>((const unsigned int*)ei);
    k_zero<<<1024, 256>>>();
    k_pre <<<(NN + 127) / 128, 256, SM_PRE>>>(x, ew1, eb1);
    k_edge<<<NE / 128, 256, SM_EDGE>>>(ea, ei, ew1, ew2, eb2, neg_, neb_, eout);
    k_node<<<(NN + 63) / 64, 256, SM_NODE>>>(x, nw1, nb1, nw2, nb2, nxg, nxb, xout);
}